// round 1
// baseline (speedup 1.0000x reference)
#include <cuda_runtime.h>
#include <cuda_bf16.h>
#include <math.h>
#include <stdint.h>

// Problem constants
#define B_  2
#define S_  2048
#define E_  2048
#define H_  16
#define KV_ 4
#define D_  128
#define WIN_ 1024

// Scratch (allocation-free rule: __device__ globals)
__device__ float g_q[(size_t)B_ * S_ * H_ * D_];    // [B*S, H*D]
__device__ float g_k[(size_t)B_ * S_ * KV_ * D_];   // [B*S, KV*D]
__device__ float g_v[(size_t)B_ * S_ * KV_ * D_];   // [B*S, KV*D]
__device__ float g_ctx[(size_t)B_ * S_ * H_ * D_];  // [B*S, H*D]

// ---------------------------------------------------------------------------
// SGEMM: C[M,N] = A[M,K] @ B[N,K]^T   (both K-major, weights row-major [N,K])
// 128x128 block tile, BK=8, 256 threads, 8x8 per thread (4+4 split layout).
// Requires M%128==0, N%128==0, K%8==0 (true for all calls here).
// ---------------------------------------------------------------------------
__global__ __launch_bounds__(256) void sgemm_nt(
    const float* __restrict__ A, const float* __restrict__ Bw,
    float* __restrict__ C, int M, int N, int K)
{
    __shared__ float As[8][128];
    __shared__ float Bs[8][128];

    const int bx = blockIdx.x;   // N tile
    const int by = blockIdx.y;   // M tile
    const int tid = threadIdx.x;
    const int tx = tid & 15;
    const int ty = tid >> 4;

    const int lrow = tid >> 1;        // 0..127
    const int lk   = (tid & 1) * 4;   // 0 or 4

    const float* Ap = A  + (size_t)(by * 128 + lrow) * K + lk;
    const float* Bp = Bw + (size_t)(bx * 128 + lrow) * K + lk;

    float acc[8][8];
    #pragma unroll
    for (int i = 0; i < 8; i++)
        #pragma unroll
        for (int j = 0; j < 8; j++) acc[i][j] = 0.f;

    for (int k0 = 0; k0 < K; k0 += 8) {
        float4 a4 = *(const float4*)(Ap + k0);
        float4 b4 = *(const float4*)(Bp + k0);
        As[lk + 0][lrow] = a4.x; As[lk + 1][lrow] = a4.y;
        As[lk + 2][lrow] = a4.z; As[lk + 3][lrow] = a4.w;
        Bs[lk + 0][lrow] = b4.x; Bs[lk + 1][lrow] = b4.y;
        Bs[lk + 2][lrow] = b4.z; Bs[lk + 3][lrow] = b4.w;
        __syncthreads();

        #pragma unroll
        for (int kk = 0; kk < 8; kk++) {
            float a[8], b[8];
            *(float4*)&a[0] = *(const float4*)&As[kk][ty * 4];
            *(float4*)&a[4] = *(const float4*)&As[kk][64 + ty * 4];
            *(float4*)&b[0] = *(const float4*)&Bs[kk][tx * 4];
            *(float4*)&b[4] = *(const float4*)&Bs[kk][64 + tx * 4];
            #pragma unroll
            for (int i = 0; i < 8; i++)
                #pragma unroll
                for (int j = 0; j < 8; j++)
                    acc[i][j] = fmaf(a[i], b[j], acc[i][j]);
        }
        __syncthreads();
    }

    const int ncol0 = bx * 128 + tx * 4;
    #pragma unroll
    for (int i = 0; i < 8; i++) {
        int m = by * 128 + ((i < 4) ? (ty * 4 + i) : (64 + ty * 4 + (i - 4)));
        float4 c0 = make_float4(acc[i][0], acc[i][1], acc[i][2], acc[i][3]);
        float4 c1 = make_float4(acc[i][4], acc[i][5], acc[i][6], acc[i][7]);
        *(float4*)&C[(size_t)m * N + ncol0]      = c0;
        *(float4*)&C[(size_t)m * N + ncol0 + 64] = c1;
    }
}

// ---------------------------------------------------------------------------
// RoPE + RMSNorm, in place on [B*S, nheads*128]. One warp per (row, head).
// out[d]    = x[d]*c[d] + x[d+64]*s[d]        (d < 64)
// out[d+64] = -x[d]*s[d] + x[d+64]*c[d]
// then row *= rsqrt(mean(row^2) + FLT_EPS)
// ---------------------------------------------------------------------------
__global__ __launch_bounds__(128) void rope_rms(
    float* __restrict__ t, const float* __restrict__ cs,
    const float* __restrict__ sn, int nheads, int total_warps)
{
    int w = (blockIdx.x * blockDim.x + threadIdx.x) >> 5;
    int lane = threadIdx.x & 31;
    if (w >= total_warps) return;
    int h  = w % nheads;
    int bs = w / nheads;
    int s  = bs % S_;

    float* row = t + (size_t)bs * (nheads * D_) + h * D_;

    float x1a = row[lane],      x1b = row[lane + 32];
    float x2a = row[lane + 64], x2b = row[lane + 96];
    float ca = cs[s * 64 + lane], cb = cs[s * 64 + lane + 32];
    float sa = sn[s * 64 + lane], sb = sn[s * 64 + lane + 32];

    float o1a =  x1a * ca + x2a * sa;
    float o1b =  x1b * cb + x2b * sb;
    float o2a = -x1a * sa + x2a * ca;
    float o2b = -x1b * sb + x2b * cb;

    float ss = o1a * o1a + o1b * o1b + o2a * o2a + o2b * o2b;
    #pragma unroll
    for (int o = 16; o; o >>= 1) ss += __shfl_xor_sync(0xffffffffu, ss, o);
    float scale = rsqrtf(ss * (1.f / 128.f) + 1.1920928955078125e-07f);

    row[lane]      = o1a * scale;
    row[lane + 32] = o1b * scale;
    row[lane + 64] = o2a * scale;
    row[lane + 96] = o2b * scale;
}

// ---------------------------------------------------------------------------
// Sliding-window causal attention (flash style, fp32).
// Block: 256 threads = 8 warps = 8 consecutive queries of one (b,h).
// Key tiles of 32 staged in smem (stride 132 floats -> conflict-free float4).
// Lane l of a warp owns key (tile+l) for scoring, dims [4l,4l+4) for output.
// ---------------------------------------------------------------------------
__global__ __launch_bounds__(256) void attn_kernel(
    const float* __restrict__ q, const float* __restrict__ k,
    const float* __restrict__ v, float* __restrict__ ctx)
{
    __shared__ float Ks[32][132];
    __shared__ float Vs[32][132];
    __shared__ float Qs[8][128];

    const int qb = blockIdx.x * 8;
    const int h  = blockIdx.y;
    const int b  = blockIdx.z;
    const int kvh = h >> 2;                 // H/KV = 4
    const int tid = threadIdx.x;
    const int w = tid >> 5, lane = tid & 31;
    const int i = qb + w;                   // this warp's query row
    const float scl = 0.08838834764831845f; // D^-0.5

    // stage Q rows (8 x 128 floats, one float4/thread)
    {
        int r = tid >> 5, c = (tid & 31) * 4;
        *(float4*)&Qs[r][c] =
            *(const float4*)&q[((size_t)(b * S_ + qb + r)) * (H_ * D_) + h * D_ + c];
    }

    float m_run = -INFINITY, l_run = 0.f;
    float4 o = make_float4(0.f, 0.f, 0.f, 0.f);

    int j0 = qb - (WIN_ - 1); if (j0 < 0) j0 = 0;
    j0 &= ~31;
    const int j1 = qb + 7;

    for (int t = j0; t <= j1; t += 32) {
        __syncthreads();
        // cooperative load of K/V tile: 32 rows x 128 dims each
        {
            int r = tid >> 3;             // 0..31 key row in tile
            int c = (tid & 7);            // base float4 column
            const float* kr = &k[((size_t)(b * S_ + t + r)) * (KV_ * D_) + kvh * D_];
            const float* vr = &v[((size_t)(b * S_ + t + r)) * (KV_ * D_) + kvh * D_];
            #pragma unroll
            for (int u = 0; u < 4; u++) {
                int c4 = (c + u * 8) * 4;
                *(float4*)&Ks[r][c4] = *(const float4*)&kr[c4];
                *(float4*)&Vs[r][c4] = *(const float4*)&vr[c4];
            }
        }
        __syncthreads();

        // score for key j = t + lane
        const int j = t + lane;
        float dot = 0.f;
        #pragma unroll
        for (int dd = 0; dd < 32; dd++) {
            float4 qq = *(const float4*)&Qs[w][dd * 4];
            float4 kk = *(const float4*)&Ks[lane][dd * 4];
            dot = fmaf(qq.x, kk.x, dot);
            dot = fmaf(qq.y, kk.y, dot);
            dot = fmaf(qq.z, kk.z, dot);
            dot = fmaf(qq.w, kk.w, dot);
        }
        bool valid = (j <= i) && (j + WIN_ > i);
        float sc = valid ? dot * scl : -INFINITY;

        float mt = sc;
        #pragma unroll
        for (int x = 16; x; x >>= 1) mt = fmaxf(mt, __shfl_xor_sync(0xffffffffu, mt, x));
        float m_new = fmaxf(m_run, mt);

        if (m_new != -INFINITY) {
            float alpha = __expf(m_run - m_new);  // m_run=-inf -> 0
            float p = __expf(sc - m_new);         // sc=-inf -> 0
            float ps = p;
            #pragma unroll
            for (int x = 16; x; x >>= 1) ps += __shfl_xor_sync(0xffffffffu, ps, x);
            l_run = l_run * alpha + ps;
            o.x *= alpha; o.y *= alpha; o.z *= alpha; o.w *= alpha;
            m_run = m_new;

            #pragma unroll
            for (int kk = 0; kk < 32; kk++) {
                float pk = __shfl_sync(0xffffffffu, p, kk);
                float4 vv = *(const float4*)&Vs[kk][lane * 4];
                o.x = fmaf(pk, vv.x, o.x);
                o.y = fmaf(pk, vv.y, o.y);
                o.z = fmaf(pk, vv.z, o.z);
                o.w = fmaf(pk, vv.w, o.w);
            }
        }
    }

    float inv = 1.f / l_run;
    float4 res = make_float4(o.x * inv, o.y * inv, o.z * inv, o.w * inv);
    *(float4*)&ctx[((size_t)(b * S_ + i)) * (H_ * D_) + h * D_ + lane * 4] = res;
}

// ---------------------------------------------------------------------------
extern "C" void kernel_launch(void* const* d_in, const int* in_sizes, int n_in,
                              void* d_out, int out_size)
{
    const float* x    = (const float*)d_in[0];
    const float* cosp = (const float*)d_in[1];
    const float* sinp = (const float*)d_in[2];
    const float* Wq   = (const float*)d_in[3];
    const float* Wk   = (const float*)d_in[4];
    const float* Wv   = (const float*)d_in[5];
    const float* Wo   = (const float*)d_in[6];
    float* out = (float*)d_out;

    float *qp, *kp, *vp, *cp;
    cudaGetSymbolAddress((void**)&qp, g_q);
    cudaGetSymbolAddress((void**)&kp, g_k);
    cudaGetSymbolAddress((void**)&vp, g_v);
    cudaGetSymbolAddress((void**)&cp, g_ctx);

    const int M = B_ * S_;      // 4096
    const int K = E_;           // 2048

    // Projections
    sgemm_nt<<<dim3((H_ * D_) / 128, M / 128), 256>>>(x, Wq, qp, M, H_ * D_, K);
    sgemm_nt<<<dim3((KV_ * D_) / 128, M / 128), 256>>>(x, Wk, kp, M, KV_ * D_, K);
    sgemm_nt<<<dim3((KV_ * D_) / 128, M / 128), 256>>>(x, Wv, vp, M, KV_ * D_, K);

    // RoPE + RMSNorm (in place)
    {
        int wq = M * H_;   // warps for q
        int wk = M * KV_;  // warps for k
        rope_rms<<<(wq + 3) / 4, 128>>>(qp, cosp, sinp, H_, wq);
        rope_rms<<<(wk + 3) / 4, 128>>>(kp, cosp, sinp, KV_, wk);
    }

    // Attention
    attn_kernel<<<dim3(S_ / 8, H_, B_), 256>>>(qp, kp, vp, cp);

    // Output projection -> d_out
    sgemm_nt<<<dim3(E_ / 128, M / 128), 256>>>(cp, Wo, out, M, E_, K);
}

// round 2
// speedup vs baseline: 1.4615x; 1.4615x over previous
#include <cuda_runtime.h>
#include <cuda_bf16.h>
#include <math.h>
#include <stdint.h>

// Problem constants
#define B_  2
#define S_  2048
#define E_  2048
#define H_  16
#define KV_ 4
#define D_  128
#define WIN_ 1024

// Scratch (allocation-free rule: __device__ globals)
__device__ float g_q[(size_t)B_ * S_ * H_ * D_];
__device__ float g_k[(size_t)B_ * S_ * KV_ * D_];
__device__ float g_v[(size_t)B_ * S_ * KV_ * D_];
__device__ float g_ctx[(size_t)B_ * S_ * H_ * D_];

// bf16 hi/lo split buffers
__device__ __nv_bfloat16 g_xhi[(size_t)B_ * S_ * E_];
__device__ __nv_bfloat16 g_xlo[(size_t)B_ * S_ * E_];
__device__ __nv_bfloat16 g_wqhi[(size_t)H_ * D_ * E_];
__device__ __nv_bfloat16 g_wqlo[(size_t)H_ * D_ * E_];
__device__ __nv_bfloat16 g_wkhi[(size_t)KV_ * D_ * E_];
__device__ __nv_bfloat16 g_wklo[(size_t)KV_ * D_ * E_];
__device__ __nv_bfloat16 g_wvhi[(size_t)KV_ * D_ * E_];
__device__ __nv_bfloat16 g_wvlo[(size_t)KV_ * D_ * E_];
__device__ __nv_bfloat16 g_wohi[(size_t)E_ * H_ * D_];
__device__ __nv_bfloat16 g_wolo[(size_t)E_ * H_ * D_];
__device__ __nv_bfloat16 g_chi[(size_t)B_ * S_ * H_ * D_];
__device__ __nv_bfloat16 g_clo[(size_t)B_ * S_ * H_ * D_];

// ---------------------------------------------------------------------------
// fp32 -> (hi, lo) bf16 split. 2 elems per thread.
// ---------------------------------------------------------------------------
__global__ __launch_bounds__(256) void split_bf16(
    const float2* __restrict__ x, __nv_bfloat162* __restrict__ hi,
    __nv_bfloat162* __restrict__ lo, int n2)
{
    int i = blockIdx.x * blockDim.x + threadIdx.x;
    if (i >= n2) return;
    float2 v = x[i];
    __nv_bfloat16 h0 = __float2bfloat16(v.x);
    __nv_bfloat16 h1 = __float2bfloat16(v.y);
    __nv_bfloat162 hh; hh.x = h0; hh.y = h1;
    __nv_bfloat162 ll;
    ll.x = __float2bfloat16(v.x - __bfloat162float(h0));
    ll.y = __float2bfloat16(v.y - __bfloat162float(h1));
    hi[i] = hh;
    lo[i] = ll;
}

// ---------------------------------------------------------------------------
// Tensor-core GEMM with bf16 error compensation (3 mma per tile pair):
//   C[M,N] = A[M,K] @ W[N,K]^T,  A,W given as bf16 hi/lo pairs, C fp32.
// 128x128x16 CTA tile, 256 threads, warp tile 64x32, cp.async double buffer.
// M%128==0, N%128==0, K%16==0 required.
// ---------------------------------------------------------------------------
#define SSTR 24                       // bf16 elems per smem row (48B: conflict-free)
#define TILE_B (128 * SSTR * 2)       // bytes per (stage,prec) tile = 6144
#define STAGE_B (2 * TILE_B)          // bytes per stage (hi+lo) = 12288

#define CP16(dst, src) \
    asm volatile("cp.async.cg.shared.global [%0], [%1], 16;\n" :: "r"(dst), "l"(src))
#define CP_COMMIT() asm volatile("cp.async.commit_group;\n" ::)
#define CP_WAIT1()  asm volatile("cp.async.wait_group 1;\n" ::)

#define LDSM4(R, addr) \
    asm volatile("ldmatrix.sync.aligned.m8n8.x4.shared.b16 {%0,%1,%2,%3}, [%4];\n" \
        : "=r"(R[0]), "=r"(R[1]), "=r"(R[2]), "=r"(R[3]) : "r"(addr))

#define MMA16816(acc, a, b0, b1) \
    asm volatile("mma.sync.aligned.m16n8k16.row.col.f32.bf16.bf16.f32 " \
        "{%0,%1,%2,%3}, {%4,%5,%6,%7}, {%8,%9}, {%0,%1,%2,%3};\n" \
        : "+f"(acc[0]), "+f"(acc[1]), "+f"(acc[2]), "+f"(acc[3]) \
        : "r"(a[0]), "r"(a[1]), "r"(a[2]), "r"(a[3]), "r"(b0), "r"(b1))

__global__ __launch_bounds__(256, 1) void gemm3(
    const __nv_bfloat16* __restrict__ Ah, const __nv_bfloat16* __restrict__ Al,
    const __nv_bfloat16* __restrict__ Bh, const __nv_bfloat16* __restrict__ Bl,
    float* __restrict__ C, int M, int N, int K)
{
    __shared__ __nv_bfloat16 sA[2][2][128 * SSTR];
    __shared__ __nv_bfloat16 sB[2][2][128 * SSTR];

    const int tid = threadIdx.x;
    const int lane = tid & 31;
    const int wid = tid >> 5;
    const int wm = wid & 1;       // 0..1
    const int wn = wid >> 1;      // 0..3
    const int bm = blockIdx.y, bn = blockIdx.x;

    const uint32_t aBase = (uint32_t)__cvta_generic_to_shared(&sA[0][0][0]);
    const uint32_t bBase = (uint32_t)__cvta_generic_to_shared(&sB[0][0][0]);

    // global staging pointers (per-thread): row = tid/2, 8-elem chunk = tid&1
    const int lrow = tid >> 1;
    const int lkc  = tid & 1;
    const __nv_bfloat16* gah = Ah + (size_t)(bm * 128 + lrow) * K + lkc * 8;
    const __nv_bfloat16* gal = Al + (size_t)(bm * 128 + lrow) * K + lkc * 8;
    const __nv_bfloat16* gbh = Bh + (size_t)(bn * 128 + lrow) * K + lkc * 8;
    const __nv_bfloat16* gbl = Bl + (size_t)(bn * 128 + lrow) * K + lkc * 8;
    const uint32_t sOff = (uint32_t)(lrow * SSTR + lkc * 8) * 2;

    // ldmatrix lane offsets
    const int rowA = wm * 64 + (lane & 15);
    const int cA   = lane >> 4;
    const uint32_t aLn = (uint32_t)(rowA * SSTR + cA * 8) * 2;
    const int rowB = wn * 32 + ((lane >> 4) << 3) + (lane & 7);
    const int cB   = (lane >> 3) & 1;
    const uint32_t bLn = (uint32_t)(rowB * SSTR + cB * 8) * 2;

    float acc[4][4][4];
    #pragma unroll
    for (int i = 0; i < 4; i++)
        #pragma unroll
        for (int j = 0; j < 4; j++)
            #pragma unroll
            for (int r = 0; r < 4; r++) acc[i][j][r] = 0.f;

    const int T = K / 16;

    // prologue: stages 0,1
    #pragma unroll
    for (int p = 0; p < 2; p++) {
        uint32_t sa = aBase + p * STAGE_B + sOff;
        uint32_t sb = bBase + p * STAGE_B + sOff;
        CP16(sa,          gah + p * 16);
        CP16(sa + TILE_B, gal + p * 16);
        CP16(sb,          gbh + p * 16);
        CP16(sb + TILE_B, gbl + p * 16);
        CP_COMMIT();
    }

    for (int t = 0; t < T; t++) {
        CP_WAIT1();
        __syncthreads();

        const uint32_t ab = aBase + (t & 1) * STAGE_B;
        const uint32_t bb = bBase + (t & 1) * STAGE_B;

        uint32_t ah[4][4], al[4][4], bh[2][4], bl[2][4];
        #pragma unroll
        for (int mt = 0; mt < 4; mt++) {
            LDSM4(ah[mt], ab + aLn + mt * (16 * SSTR * 2));
            LDSM4(al[mt], ab + TILE_B + aLn + mt * (16 * SSTR * 2));
        }
        #pragma unroll
        for (int pr = 0; pr < 2; pr++) {
            LDSM4(bh[pr], bb + bLn + pr * (16 * SSTR * 2));
            LDSM4(bl[pr], bb + TILE_B + bLn + pr * (16 * SSTR * 2));
        }

        #pragma unroll
        for (int mt = 0; mt < 4; mt++)
            #pragma unroll
            for (int nt = 0; nt < 4; nt++) {
                const int pr = nt >> 1, sb2 = (nt & 1) * 2;
                MMA16816(acc[mt][nt], ah[mt], bh[pr][sb2], bh[pr][sb2 + 1]);
                MMA16816(acc[mt][nt], ah[mt], bl[pr][sb2], bl[pr][sb2 + 1]);
                MMA16816(acc[mt][nt], al[mt], bh[pr][sb2], bh[pr][sb2 + 1]);
            }

        __syncthreads();
        if (t + 2 < T) {
            uint32_t sa = aBase + (t & 1) * STAGE_B + sOff;
            uint32_t sb = bBase + (t & 1) * STAGE_B + sOff;
            CP16(sa,          gah + (t + 2) * 16);
            CP16(sa + TILE_B, gal + (t + 2) * 16);
            CP16(sb,          gbh + (t + 2) * 16);
            CP16(sb + TILE_B, gbl + (t + 2) * 16);
        }
        CP_COMMIT();
    }

    // epilogue
    #pragma unroll
    for (int mt = 0; mt < 4; mt++) {
        const int r0 = bm * 128 + wm * 64 + mt * 16 + (lane >> 2);
        #pragma unroll
        for (int nt = 0; nt < 4; nt++) {
            const int c0 = bn * 128 + wn * 32 + nt * 8 + (lane & 3) * 2;
            float2 v0 = make_float2(acc[mt][nt][0], acc[mt][nt][1]);
            float2 v1 = make_float2(acc[mt][nt][2], acc[mt][nt][3]);
            *(float2*)&C[(size_t)r0 * N + c0]       = v0;
            *(float2*)&C[(size_t)(r0 + 8) * N + c0] = v1;
        }
    }
}

// ---------------------------------------------------------------------------
// RoPE + RMSNorm, in place on [B*S, nheads*128]. One warp per (row, head).
// ---------------------------------------------------------------------------
__global__ __launch_bounds__(128) void rope_rms(
    float* __restrict__ t, const float* __restrict__ cs,
    const float* __restrict__ sn, int nheads, int total_warps)
{
    int w = (blockIdx.x * blockDim.x + threadIdx.x) >> 5;
    int lane = threadIdx.x & 31;
    if (w >= total_warps) return;
    int h  = w % nheads;
    int bs = w / nheads;
    int s  = bs % S_;

    float* row = t + (size_t)bs * (nheads * D_) + h * D_;

    float x1a = row[lane],      x1b = row[lane + 32];
    float x2a = row[lane + 64], x2b = row[lane + 96];
    float ca = cs[s * 64 + lane], cb = cs[s * 64 + lane + 32];
    float sa = sn[s * 64 + lane], sb = sn[s * 64 + lane + 32];

    float o1a =  x1a * ca + x2a * sa;
    float o1b =  x1b * cb + x2b * sb;
    float o2a = -x1a * sa + x2a * ca;
    float o2b = -x1b * sb + x2b * cb;

    float ss = o1a * o1a + o1b * o1b + o2a * o2a + o2b * o2b;
    #pragma unroll
    for (int o = 16; o; o >>= 1) ss += __shfl_xor_sync(0xffffffffu, ss, o);
    float scale = rsqrtf(ss * (1.f / 128.f) + 1.1920928955078125e-07f);

    row[lane]      = o1a * scale;
    row[lane + 32] = o1b * scale;
    row[lane + 64] = o2a * scale;
    row[lane + 96] = o2b * scale;
}

// ---------------------------------------------------------------------------
// Sliding-window causal attention (flash style, fp32). Unchanged from R1.
// ---------------------------------------------------------------------------
__global__ __launch_bounds__(256) void attn_kernel(
    const float* __restrict__ q, const float* __restrict__ k,
    const float* __restrict__ v, float* __restrict__ ctx)
{
    __shared__ float Ks[32][132];
    __shared__ float Vs[32][132];
    __shared__ float Qs[8][128];

    const int qb = blockIdx.x * 8;
    const int h  = blockIdx.y;
    const int b  = blockIdx.z;
    const int kvh = h >> 2;
    const int tid = threadIdx.x;
    const int w = tid >> 5, lane = tid & 31;
    const int i = qb + w;
    const float scl = 0.08838834764831845f;

    {
        int r = tid >> 5, c = (tid & 31) * 4;
        *(float4*)&Qs[r][c] =
            *(const float4*)&q[((size_t)(b * S_ + qb + r)) * (H_ * D_) + h * D_ + c];
    }

    float m_run = -INFINITY, l_run = 0.f;
    float4 o = make_float4(0.f, 0.f, 0.f, 0.f);

    int j0 = qb - (WIN_ - 1); if (j0 < 0) j0 = 0;
    j0 &= ~31;
    const int j1 = qb + 7;

    for (int t = j0; t <= j1; t += 32) {
        __syncthreads();
        {
            int r = tid >> 3;
            int c = (tid & 7);
            const float* kr = &k[((size_t)(b * S_ + t + r)) * (KV_ * D_) + kvh * D_];
            const float* vr = &v[((size_t)(b * S_ + t + r)) * (KV_ * D_) + kvh * D_];
            #pragma unroll
            for (int u = 0; u < 4; u++) {
                int c4 = (c + u * 8) * 4;
                *(float4*)&Ks[r][c4] = *(const float4*)&kr[c4];
                *(float4*)&Vs[r][c4] = *(const float4*)&vr[c4];
            }
        }
        __syncthreads();

        const int j = t + lane;
        float dot = 0.f;
        #pragma unroll
        for (int dd = 0; dd < 32; dd++) {
            float4 qq = *(const float4*)&Qs[w][dd * 4];
            float4 kk = *(const float4*)&Ks[lane][dd * 4];
            dot = fmaf(qq.x, kk.x, dot);
            dot = fmaf(qq.y, kk.y, dot);
            dot = fmaf(qq.z, kk.z, dot);
            dot = fmaf(qq.w, kk.w, dot);
        }
        bool valid = (j <= i) && (j + WIN_ > i);
        float sc = valid ? dot * scl : -INFINITY;

        float mt = sc;
        #pragma unroll
        for (int x = 16; x; x >>= 1) mt = fmaxf(mt, __shfl_xor_sync(0xffffffffu, mt, x));
        float m_new = fmaxf(m_run, mt);

        if (m_new != -INFINITY) {
            float alpha = __expf(m_run - m_new);
            float p = __expf(sc - m_new);
            float ps = p;
            #pragma unroll
            for (int x = 16; x; x >>= 1) ps += __shfl_xor_sync(0xffffffffu, ps, x);
            l_run = l_run * alpha + ps;
            o.x *= alpha; o.y *= alpha; o.z *= alpha; o.w *= alpha;
            m_run = m_new;

            #pragma unroll
            for (int kk = 0; kk < 32; kk++) {
                float pk = __shfl_sync(0xffffffffu, p, kk);
                float4 vv = *(const float4*)&Vs[kk][lane * 4];
                o.x = fmaf(pk, vv.x, o.x);
                o.y = fmaf(pk, vv.y, o.y);
                o.z = fmaf(pk, vv.z, o.z);
                o.w = fmaf(pk, vv.w, o.w);
            }
        }
    }

    float inv = 1.f / l_run;
    float4 res = make_float4(o.x * inv, o.y * inv, o.z * inv, o.w * inv);
    *(float4*)&ctx[((size_t)(b * S_ + i)) * (H_ * D_) + h * D_ + lane * 4] = res;
}

// ---------------------------------------------------------------------------
extern "C" void kernel_launch(void* const* d_in, const int* in_sizes, int n_in,
                              void* d_out, int out_size)
{
    const float* x    = (const float*)d_in[0];
    const float* cosp = (const float*)d_in[1];
    const float* sinp = (const float*)d_in[2];
    const float* Wq   = (const float*)d_in[3];
    const float* Wk   = (const float*)d_in[4];
    const float* Wv   = (const float*)d_in[5];
    const float* Wo   = (const float*)d_in[6];
    float* out = (float*)d_out;

    float *qp, *kp, *vp, *cp;
    cudaGetSymbolAddress((void**)&qp, g_q);
    cudaGetSymbolAddress((void**)&kp, g_k);
    cudaGetSymbolAddress((void**)&vp, g_v);
    cudaGetSymbolAddress((void**)&cp, g_ctx);

    __nv_bfloat16 *xhi, *xlo, *wqhi, *wqlo, *wkhi, *wklo, *wvhi, *wvlo, *wohi, *wolo, *chi, *clo;
    cudaGetSymbolAddress((void**)&xhi, g_xhi);
    cudaGetSymbolAddress((void**)&xlo, g_xlo);
    cudaGetSymbolAddress((void**)&wqhi, g_wqhi);
    cudaGetSymbolAddress((void**)&wqlo, g_wqlo);
    cudaGetSymbolAddress((void**)&wkhi, g_wkhi);
    cudaGetSymbolAddress((void**)&wklo, g_wklo);
    cudaGetSymbolAddress((void**)&wvhi, g_wvhi);
    cudaGetSymbolAddress((void**)&wvlo, g_wvlo);
    cudaGetSymbolAddress((void**)&wohi, g_wohi);
    cudaGetSymbolAddress((void**)&wolo, g_wolo);
    cudaGetSymbolAddress((void**)&chi, g_chi);
    cudaGetSymbolAddress((void**)&clo, g_clo);

    const int M = B_ * S_;      // 4096
    const int K = E_;           // 2048

    // splits
    {
        int nx = M * E_ / 2;
        split_bf16<<<(nx + 255) / 256, 256>>>((const float2*)x,
            (__nv_bfloat162*)xhi, (__nv_bfloat162*)xlo, nx);
        int nq = H_ * D_ * E_ / 2;
        split_bf16<<<(nq + 255) / 256, 256>>>((const float2*)Wq,
            (__nv_bfloat162*)wqhi, (__nv_bfloat162*)wqlo, nq);
        int nk = KV_ * D_ * E_ / 2;
        split_bf16<<<(nk + 255) / 256, 256>>>((const float2*)Wk,
            (__nv_bfloat162*)wkhi, (__nv_bfloat162*)wklo, nk);
        split_bf16<<<(nk + 255) / 256, 256>>>((const float2*)Wv,
            (__nv_bfloat162*)wvhi, (__nv_bfloat162*)wvlo, nk);
        int no = E_ * H_ * D_ / 2;
        split_bf16<<<(no + 255) / 256, 256>>>((const float2*)Wo,
            (__nv_bfloat162*)wohi, (__nv_bfloat162*)wolo, no);
    }

    // projections (tensor cores)
    gemm3<<<dim3((H_ * D_) / 128, M / 128), 256>>>(xhi, xlo, wqhi, wqlo, qp, M, H_ * D_, K);
    gemm3<<<dim3((KV_ * D_) / 128, M / 128), 256>>>(xhi, xlo, wkhi, wklo, kp, M, KV_ * D_, K);
    gemm3<<<dim3((KV_ * D_) / 128, M / 128), 256>>>(xhi, xlo, wvhi, wvlo, vp, M, KV_ * D_, K);

    // RoPE + RMSNorm
    {
        int wq = M * H_;
        int wk = M * KV_;
        rope_rms<<<(wq + 3) / 4, 128>>>(qp, cosp, sinp, H_, wq);
        rope_rms<<<(wk + 3) / 4, 128>>>(kp, cosp, sinp, KV_, wk);
    }

    // attention
    attn_kernel<<<dim3(S_ / 8, H_, B_), 256>>>(qp, kp, vp, cp);

    // ctx split + output projection
    {
        int nc = M * H_ * D_ / 2;
        split_bf16<<<(nc + 255) / 256, 256>>>((const float2*)cp,
            (__nv_bfloat162*)chi, (__nv_bfloat162*)clo, nc);
    }
    gemm3<<<dim3(E_ / 128, M / 128), 256>>>(chi, clo, wohi, wolo, out, M, E_, K);
}

// round 3
// speedup vs baseline: 3.8301x; 2.6207x over previous
#include <cuda_runtime.h>
#include <cuda_bf16.h>
#include <math.h>
#include <stdint.h>

#define B_  2
#define S_  2048
#define E_  2048
#define H_  16
#define KV_ 4
#define D_  128
#define WIN_ 1024

// Scratch
__device__ float g_q[(size_t)B_ * S_ * H_ * D_];
__device__ float g_k[(size_t)B_ * S_ * KV_ * D_];
__device__ float g_v[(size_t)B_ * S_ * KV_ * D_];

__device__ __nv_bfloat16 g_xhi[(size_t)B_ * S_ * E_];
__device__ __nv_bfloat16 g_xlo[(size_t)B_ * S_ * E_];
__device__ __nv_bfloat16 g_wqhi[(size_t)H_ * D_ * E_];
__device__ __nv_bfloat16 g_wqlo[(size_t)H_ * D_ * E_];
__device__ __nv_bfloat16 g_wkhi[(size_t)KV_ * D_ * E_];
__device__ __nv_bfloat16 g_wklo[(size_t)KV_ * D_ * E_];
__device__ __nv_bfloat16 g_wvhi[(size_t)KV_ * D_ * E_];
__device__ __nv_bfloat16 g_wvlo[(size_t)KV_ * D_ * E_];
__device__ __nv_bfloat16 g_wohi[(size_t)E_ * H_ * D_];
__device__ __nv_bfloat16 g_wolo[(size_t)E_ * H_ * D_];
__device__ __nv_bfloat16 g_chi[(size_t)B_ * S_ * H_ * D_];
__device__ __nv_bfloat16 g_clo[(size_t)B_ * S_ * H_ * D_];
__device__ __nv_bfloat16 g_qhi[(size_t)B_ * S_ * H_ * D_];
__device__ __nv_bfloat16 g_qlo[(size_t)B_ * S_ * H_ * D_];
__device__ __nv_bfloat16 g_khi[(size_t)B_ * S_ * KV_ * D_];
__device__ __nv_bfloat16 g_klo[(size_t)B_ * S_ * KV_ * D_];
__device__ __nv_bfloat16 g_vhi[(size_t)B_ * S_ * KV_ * D_];
__device__ __nv_bfloat16 g_vlo[(size_t)B_ * S_ * KV_ * D_];

// ---------------------------------------------------------------------------
__global__ __launch_bounds__(256) void split_bf16(
    const float2* __restrict__ x, __nv_bfloat162* __restrict__ hi,
    __nv_bfloat162* __restrict__ lo, int n2)
{
    int i = blockIdx.x * blockDim.x + threadIdx.x;
    if (i >= n2) return;
    float2 v = x[i];
    __nv_bfloat16 h0 = __float2bfloat16(v.x);
    __nv_bfloat16 h1 = __float2bfloat16(v.y);
    __nv_bfloat162 hh; hh.x = h0; hh.y = h1;
    __nv_bfloat162 ll;
    ll.x = __float2bfloat16(v.x - __bfloat162float(h0));
    ll.y = __float2bfloat16(v.y - __bfloat162float(h1));
    hi[i] = hh;
    lo[i] = ll;
}

// ---------------------------------------------------------------------------
// PTX helpers
// ---------------------------------------------------------------------------
#define CP16(dst, src) \
    asm volatile("cp.async.cg.shared.global [%0], [%1], 16;\n" :: "r"(dst), "l"(src))
#define CP_COMMIT() asm volatile("cp.async.commit_group;\n" ::)
#define CP_WAIT1()  asm volatile("cp.async.wait_group 1;\n" ::)
#define CP_WAIT0()  asm volatile("cp.async.wait_group 0;\n" ::)

#define LDSM4(R, addr) \
    asm volatile("ldmatrix.sync.aligned.m8n8.x4.shared.b16 {%0,%1,%2,%3}, [%4];\n" \
        : "=r"(R[0]), "=r"(R[1]), "=r"(R[2]), "=r"(R[3]) : "r"(addr))
#define LDSM4T(R, addr) \
    asm volatile("ldmatrix.sync.aligned.m8n8.x4.trans.shared.b16 {%0,%1,%2,%3}, [%4];\n" \
        : "=r"(R[0]), "=r"(R[1]), "=r"(R[2]), "=r"(R[3]) : "r"(addr))

#define MMA16816(acc, a, b0, b1) \
    asm volatile("mma.sync.aligned.m16n8k16.row.col.f32.bf16.bf16.f32 " \
        "{%0,%1,%2,%3}, {%4,%5,%6,%7}, {%8,%9}, {%0,%1,%2,%3};\n" \
        : "+f"(acc[0]), "+f"(acc[1]), "+f"(acc[2]), "+f"(acc[3]) \
        : "r"(a[0]), "r"(a[1]), "r"(a[2]), "r"(a[3]), "r"(b0), "r"(b1))

// ---------------------------------------------------------------------------
// gemm3: C[M,N] = A @ W^T with bf16 hi/lo compensation (unchanged from R2)
// ---------------------------------------------------------------------------
#define SSTR 24
#define TILE_B (128 * SSTR * 2)
#define STAGE_B (2 * TILE_B)

__global__ __launch_bounds__(256, 1) void gemm3(
    const __nv_bfloat16* __restrict__ Ah, const __nv_bfloat16* __restrict__ Al,
    const __nv_bfloat16* __restrict__ Bh, const __nv_bfloat16* __restrict__ Bl,
    float* __restrict__ C, int M, int N, int K)
{
    __shared__ __nv_bfloat16 sA[2][2][128 * SSTR];
    __shared__ __nv_bfloat16 sB[2][2][128 * SSTR];

    const int tid = threadIdx.x;
    const int lane = tid & 31;
    const int wid = tid >> 5;
    const int wm = wid & 1;
    const int wn = wid >> 1;
    const int bm = blockIdx.y, bn = blockIdx.x;

    const uint32_t aBase = (uint32_t)__cvta_generic_to_shared(&sA[0][0][0]);
    const uint32_t bBase = (uint32_t)__cvta_generic_to_shared(&sB[0][0][0]);

    const int lrow = tid >> 1;
    const int lkc  = tid & 1;
    const __nv_bfloat16* gah = Ah + (size_t)(bm * 128 + lrow) * K + lkc * 8;
    const __nv_bfloat16* gal = Al + (size_t)(bm * 128 + lrow) * K + lkc * 8;
    const __nv_bfloat16* gbh = Bh + (size_t)(bn * 128 + lrow) * K + lkc * 8;
    const __nv_bfloat16* gbl = Bl + (size_t)(bn * 128 + lrow) * K + lkc * 8;
    const uint32_t sOff = (uint32_t)(lrow * SSTR + lkc * 8) * 2;

    const int rowA = wm * 64 + (lane & 15);
    const int cA   = lane >> 4;
    const uint32_t aLn = (uint32_t)(rowA * SSTR + cA * 8) * 2;
    const int rowB = wn * 32 + ((lane >> 4) << 3) + (lane & 7);
    const int cB   = (lane >> 3) & 1;
    const uint32_t bLn = (uint32_t)(rowB * SSTR + cB * 8) * 2;

    float acc[4][4][4];
    #pragma unroll
    for (int i = 0; i < 4; i++)
        #pragma unroll
        for (int j = 0; j < 4; j++)
            #pragma unroll
            for (int r = 0; r < 4; r++) acc[i][j][r] = 0.f;

    const int T = K / 16;

    #pragma unroll
    for (int p = 0; p < 2; p++) {
        uint32_t sa = aBase + p * STAGE_B + sOff;
        uint32_t sb = bBase + p * STAGE_B + sOff;
        CP16(sa,          gah + p * 16);
        CP16(sa + TILE_B, gal + p * 16);
        CP16(sb,          gbh + p * 16);
        CP16(sb + TILE_B, gbl + p * 16);
        CP_COMMIT();
    }

    for (int t = 0; t < T; t++) {
        CP_WAIT1();
        __syncthreads();

        const uint32_t ab = aBase + (t & 1) * STAGE_B;
        const uint32_t bb = bBase + (t & 1) * STAGE_B;

        uint32_t ah[4][4], al[4][4], bh[2][4], bl[2][4];
        #pragma unroll
        for (int mt = 0; mt < 4; mt++) {
            LDSM4(ah[mt], ab + aLn + mt * (16 * SSTR * 2));
            LDSM4(al[mt], ab + TILE_B + aLn + mt * (16 * SSTR * 2));
        }
        #pragma unroll
        for (int pr = 0; pr < 2; pr++) {
            LDSM4(bh[pr], bb + bLn + pr * (16 * SSTR * 2));
            LDSM4(bl[pr], bb + TILE_B + bLn + pr * (16 * SSTR * 2));
        }

        #pragma unroll
        for (int mt = 0; mt < 4; mt++)
            #pragma unroll
            for (int nt = 0; nt < 4; nt++) {
                const int pr = nt >> 1, sb2 = (nt & 1) * 2;
                MMA16816(acc[mt][nt], ah[mt], bh[pr][sb2], bh[pr][sb2 + 1]);
                MMA16816(acc[mt][nt], ah[mt], bl[pr][sb2], bl[pr][sb2 + 1]);
                MMA16816(acc[mt][nt], al[mt], bh[pr][sb2], bh[pr][sb2 + 1]);
            }

        __syncthreads();
        if (t + 2 < T) {
            uint32_t sa = aBase + (t & 1) * STAGE_B + sOff;
            uint32_t sb = bBase + (t & 1) * STAGE_B + sOff;
            CP16(sa,          gah + (t + 2) * 16);
            CP16(sa + TILE_B, gal + (t + 2) * 16);
            CP16(sb,          gbh + (t + 2) * 16);
            CP16(sb + TILE_B, gbl + (t + 2) * 16);
        }
        CP_COMMIT();
    }

    #pragma unroll
    for (int mt = 0; mt < 4; mt++) {
        const int r0 = bm * 128 + wm * 64 + mt * 16 + (lane >> 2);
        #pragma unroll
        for (int nt = 0; nt < 4; nt++) {
            const int c0 = bn * 128 + wn * 32 + nt * 8 + (lane & 3) * 2;
            float2 v0 = make_float2(acc[mt][nt][0], acc[mt][nt][1]);
            float2 v1 = make_float2(acc[mt][nt][2], acc[mt][nt][3]);
            *(float2*)&C[(size_t)r0 * N + c0]       = v0;
            *(float2*)&C[(size_t)(r0 + 8) * N + c0] = v1;
        }
    }
}

// ---------------------------------------------------------------------------
// RoPE + RMSNorm -> bf16 hi/lo output. One warp per (row, head).
// ---------------------------------------------------------------------------
__global__ __launch_bounds__(128) void rope_rms_split(
    const float* __restrict__ t, __nv_bfloat16* __restrict__ hi,
    __nv_bfloat16* __restrict__ lo, const float* __restrict__ cs,
    const float* __restrict__ sn, int nheads, int total_warps)
{
    int w = (blockIdx.x * blockDim.x + threadIdx.x) >> 5;
    int lane = threadIdx.x & 31;
    if (w >= total_warps) return;
    int h  = w % nheads;
    int bs = w / nheads;
    int s  = bs % S_;

    size_t base = (size_t)bs * (nheads * D_) + h * D_;
    const float* row = t + base;

    float x1a = row[lane],      x1b = row[lane + 32];
    float x2a = row[lane + 64], x2b = row[lane + 96];
    float ca = cs[s * 64 + lane], cb = cs[s * 64 + lane + 32];
    float sa = sn[s * 64 + lane], sb = sn[s * 64 + lane + 32];

    float o1a =  x1a * ca + x2a * sa;
    float o1b =  x1b * cb + x2b * sb;
    float o2a = -x1a * sa + x2a * ca;
    float o2b = -x1b * sb + x2b * cb;

    float ss = o1a * o1a + o1b * o1b + o2a * o2a + o2b * o2b;
    #pragma unroll
    for (int o = 16; o; o >>= 1) ss += __shfl_xor_sync(0xffffffffu, ss, o);
    float scale = rsqrtf(ss * (1.f / 128.f) + 1.1920928955078125e-07f);

    float v[4] = {o1a * scale, o1b * scale, o2a * scale, o2b * scale};
    int off[4] = {lane, lane + 32, lane + 64, lane + 96};
    #pragma unroll
    for (int u = 0; u < 4; u++) {
        __nv_bfloat16 hh = __float2bfloat16(v[u]);
        hi[base + off[u]] = hh;
        lo[base + off[u]] = __float2bfloat16(v[u] - __bfloat162float(hh));
    }
}

// ---------------------------------------------------------------------------
// Tensor-core sliding-window flash attention with bf16 hi/lo compensation.
// 256 threads = 8 warps; q-tile 128 (16 rows/warp); k-tiles of 64.
// ---------------------------------------------------------------------------
#define RB 17408   // 64 rows * 272 B (stride 136 bf16)

__global__ __launch_bounds__(256) void attn_mma(
    const __nv_bfloat16* __restrict__ qh, const __nv_bfloat16* __restrict__ ql,
    const __nv_bfloat16* __restrict__ kh, const __nv_bfloat16* __restrict__ kl,
    const __nv_bfloat16* __restrict__ vh, const __nv_bfloat16* __restrict__ vl,
    __nv_bfloat16* __restrict__ chi, __nv_bfloat16* __restrict__ clo)
{
    extern __shared__ char smem[];
    const uint32_t sbase = (uint32_t)__cvta_generic_to_shared(smem);

    const int tid = threadIdx.x, lane = tid & 31, w = tid >> 5;
    const int q0 = blockIdx.x * 128;
    const int h  = blockIdx.y, b = blockIdx.z;
    const int kvh = h >> 2;
    const float scl = 0.08838834764831845f;

    // ---- stage Q (hi -> region 0..2RB, lo -> region 4RB..6RB) ----
    {
        int r = tid >> 1;
        size_t gbase = ((size_t)(b * S_ + q0 + r)) * (H_ * D_) + h * D_;
        const uint4* gh = (const uint4*)(qh + gbase);
        const uint4* gl = (const uint4*)(ql + gbase);
        #pragma unroll
        for (int u = 0; u < 8; u++) {
            int c = (tid & 1) * 8 + u;
            *(uint4*)(smem + (size_t)r * 272 + c * 16)            = gh[c];
            *(uint4*)(smem + 4 * RB + (size_t)r * 272 + c * 16)   = gl[c];
        }
    }
    __syncthreads();

    // ---- Q A-fragments into registers (persist whole CTA) ----
    uint32_t ah[8][4], al[8][4];
    {
        uint32_t qro = (uint32_t)((w * 16 + (lane & 15)) * 272);
        #pragma unroll
        for (int d = 0; d < 8; d++) {
            uint32_t co = (uint32_t)((d * 16 + (lane >> 4) * 8) * 2);
            LDSM4(ah[d], sbase + qro + co);
            LDSM4(al[d], sbase + 4 * RB + qro + co);
        }
    }
    __syncthreads();

    float pacc[16][4];
    #pragma unroll
    for (int g = 0; g < 16; g++)
        #pragma unroll
        for (int r = 0; r < 4; r++) pacc[g][r] = 0.f;

    float m_run0 = -1e30f, m_run1 = -1e30f, l0 = 0.f, l1 = 0.f;

    const int ibase = q0 + w * 16;
    const int i0 = ibase + (lane >> 2);
    const int i1 = i0 + 8;

    int t0 = q0 - 1024; if (t0 < 0) t0 = 0;
    const int n = (q0 + 128 - t0) >> 6;

    // cp.async staging lanes
    const int crow = tid >> 2;
    const size_t grow = ((size_t)b * S_) * (KV_ * D_) + (size_t)kvh * D_;

    // prologue: tile 0 -> stage 0
    {
        size_t gb = grow + (size_t)(t0 + crow) * (KV_ * D_);
        #pragma unroll
        for (int u = 0; u < 4; u++) {
            int c = (tid & 3) * 4 + u;
            uint32_t so = (uint32_t)(crow * 272 + c * 16);
            CP16(sbase + so,          kh + gb + c * 8);
            CP16(sbase + 2 * RB + so, kl + gb + c * 8);
            CP16(sbase + 4 * RB + so, vh + gb + c * 8);
            CP16(sbase + 6 * RB + so, vl + gb + c * 8);
        }
        CP_COMMIT();
    }

    for (int it = 0; it < n; it++) {
        const int t = t0 + it * 64;
        if (it + 1 < n) {
            int st = (it + 1) & 1;
            size_t gb = grow + (size_t)(t + 64 + crow) * (KV_ * D_);
            #pragma unroll
            for (int u = 0; u < 4; u++) {
                int c = (tid & 3) * 4 + u;
                uint32_t so = (uint32_t)(st * RB + crow * 272 + c * 16);
                CP16(sbase + so,          kh + gb + c * 8);
                CP16(sbase + 2 * RB + so, kl + gb + c * 8);
                CP16(sbase + 4 * RB + so, vh + gb + c * 8);
                CP16(sbase + 6 * RB + so, vl + gb + c * 8);
            }
            CP_COMMIT();
            CP_WAIT1();
        } else {
            CP_WAIT0();
        }
        __syncthreads();

        const uint32_t khb = sbase + (it & 1) * RB;
        const uint32_t klb = khb + 2 * RB;
        const uint32_t vhb = khb + 4 * RB;
        const uint32_t vlb = khb + 6 * RB;

        // ---- S = Q K^T (3-mma compensation) ----
        float sacc[8][4];
        #pragma unroll
        for (int g = 0; g < 8; g++)
            #pragma unroll
            for (int r = 0; r < 4; r++) sacc[g][r] = 0.f;

        #pragma unroll
        for (int d = 0; d < 8; d++) {
            uint32_t co = (uint32_t)((d * 16 + ((lane >> 3) & 1) * 8) * 2);
            #pragma unroll
            for (int g = 0; g < 4; g++) {
                uint32_t ro = (uint32_t)((g * 16 + ((lane >> 4) << 3) + (lane & 7)) * 272);
                uint32_t k4h[4], k4l[4];
                LDSM4(k4h, khb + ro + co);
                LDSM4(k4l, klb + ro + co);
                MMA16816(sacc[2 * g],     ah[d], k4h[0], k4h[1]);
                MMA16816(sacc[2 * g],     ah[d], k4l[0], k4l[1]);
                MMA16816(sacc[2 * g],     al[d], k4h[0], k4h[1]);
                MMA16816(sacc[2 * g + 1], ah[d], k4h[2], k4h[3]);
                MMA16816(sacc[2 * g + 1], ah[d], k4l[2], k4l[3]);
                MMA16816(sacc[2 * g + 1], al[d], k4h[2], k4h[3]);
            }
        }

        // ---- mask + online softmax ----
        const bool need_mask = (t + 63 >= ibase) || (t + 1009 <= ibase);
        float m0 = -INFINITY, m1 = -INFINITY;
        #pragma unroll
        for (int g = 0; g < 8; g++) {
            int jb = t + g * 8 + 2 * (lane & 3);
            float s0 = sacc[g][0] * scl, s1 = sacc[g][1] * scl;
            float s2 = sacc[g][2] * scl, s3 = sacc[g][3] * scl;
            if (need_mask) {
                s0 = ((jb     <= i0) && (i0 - jb < 1024))     ? s0 : -INFINITY;
                s1 = ((jb + 1 <= i0) && (i0 - jb - 1 < 1024)) ? s1 : -INFINITY;
                s2 = ((jb     <= i1) && (i1 - jb < 1024))     ? s2 : -INFINITY;
                s3 = ((jb + 1 <= i1) && (i1 - jb - 1 < 1024)) ? s3 : -INFINITY;
            }
            sacc[g][0] = s0; sacc[g][1] = s1; sacc[g][2] = s2; sacc[g][3] = s3;
            m0 = fmaxf(m0, fmaxf(s0, s1));
            m1 = fmaxf(m1, fmaxf(s2, s3));
        }
        m0 = fmaxf(m0, __shfl_xor_sync(0xffffffffu, m0, 1));
        m0 = fmaxf(m0, __shfl_xor_sync(0xffffffffu, m0, 2));
        m1 = fmaxf(m1, __shfl_xor_sync(0xffffffffu, m1, 1));
        m1 = fmaxf(m1, __shfl_xor_sync(0xffffffffu, m1, 2));

        float mn0 = fmaxf(m_run0, m0), mn1 = fmaxf(m_run1, m1);
        float a0 = __expf(m_run0 - mn0), a1 = __expf(m_run1 - mn1);
        m_run0 = mn0; m_run1 = mn1;

        float rs0 = 0.f, rs1 = 0.f;
        #pragma unroll
        for (int g = 0; g < 8; g++) {
            float p0 = __expf(sacc[g][0] - mn0);
            float p1 = __expf(sacc[g][1] - mn0);
            float p2 = __expf(sacc[g][2] - mn1);
            float p3 = __expf(sacc[g][3] - mn1);
            sacc[g][0] = p0; sacc[g][1] = p1; sacc[g][2] = p2; sacc[g][3] = p3;
            rs0 += p0 + p1; rs1 += p2 + p3;
        }
        rs0 += __shfl_xor_sync(0xffffffffu, rs0, 1);
        rs0 += __shfl_xor_sync(0xffffffffu, rs0, 2);
        rs1 += __shfl_xor_sync(0xffffffffu, rs1, 1);
        rs1 += __shfl_xor_sync(0xffffffffu, rs1, 2);
        l0 = l0 * a0 + rs0;
        l1 = l1 * a1 + rs1;

        #pragma unroll
        for (int g = 0; g < 16; g++) {
            pacc[g][0] *= a0; pacc[g][1] *= a0;
            pacc[g][2] *= a1; pacc[g][3] *= a1;
        }

        // ---- P hi/lo A-fragments ----
        uint32_t ph[4][4], pl[4][4];
        #pragma unroll
        for (int kt = 0; kt < 4; kt++) {
            #pragma unroll
            for (int qq = 0; qq < 2; qq++) {
                #pragma unroll
                for (int r2 = 0; r2 < 2; r2++) {
                    float x0 = sacc[2 * kt + qq][r2 * 2];
                    float x1 = sacc[2 * kt + qq][r2 * 2 + 1];
                    __nv_bfloat162 hh = __floats2bfloat162_rn(x0, x1);
                    __nv_bfloat162 ll = __floats2bfloat162_rn(
                        x0 - __bfloat162float(hh.x), x1 - __bfloat162float(hh.y));
                    ph[kt][qq * 2 + r2] = *(uint32_t*)&hh;
                    pl[kt][qq * 2 + r2] = *(uint32_t*)&ll;
                }
            }
        }

        // ---- O += P V (3-mma compensation), V via ldmatrix.trans ----
        #pragma unroll
        for (int kt = 0; kt < 4; kt++) {
            uint32_t ro = (uint32_t)((kt * 16 + (lane & 15)) * 272);
            uint32_t co = (uint32_t)(((lane >> 4) * 8) * 2);
            #pragma unroll
            for (int g = 0; g < 8; g++) {
                uint32_t v4h[4], v4l[4];
                LDSM4T(v4h, vhb + ro + co + g * 32);
                LDSM4T(v4l, vlb + ro + co + g * 32);
                MMA16816(pacc[2 * g],     ph[kt], v4h[0], v4h[1]);
                MMA16816(pacc[2 * g],     pl[kt], v4h[0], v4h[1]);
                MMA16816(pacc[2 * g],     ph[kt], v4l[0], v4l[1]);
                MMA16816(pacc[2 * g + 1], ph[kt], v4h[2], v4h[3]);
                MMA16816(pacc[2 * g + 1], pl[kt], v4h[2], v4h[3]);
                MMA16816(pacc[2 * g + 1], ph[kt], v4l[2], v4l[3]);
            }
        }
        __syncthreads();
    }

    // ---- epilogue: normalize + write ctx hi/lo (bf16) ----
    float inv0 = 1.f / l0, inv1 = 1.f / l1;
    size_t base0 = ((size_t)(b * S_ + i0)) * (H_ * D_) + h * D_;
    size_t base1 = base0 + (size_t)8 * (H_ * D_);
    #pragma unroll
    for (int g = 0; g < 16; g++) {
        int col = g * 8 + 2 * (lane & 3);
        float o0 = pacc[g][0] * inv0, o1 = pacc[g][1] * inv0;
        float o2 = pacc[g][2] * inv1, o3 = pacc[g][3] * inv1;
        __nv_bfloat162 h0 = __floats2bfloat162_rn(o0, o1);
        __nv_bfloat162 l0v = __floats2bfloat162_rn(
            o0 - __bfloat162float(h0.x), o1 - __bfloat162float(h0.y));
        __nv_bfloat162 h1 = __floats2bfloat162_rn(o2, o3);
        __nv_bfloat162 l1v = __floats2bfloat162_rn(
            o2 - __bfloat162float(h1.x), o3 - __bfloat162float(h1.y));
        *(uint32_t*)&chi[base0 + col] = *(uint32_t*)&h0;
        *(uint32_t*)&clo[base0 + col] = *(uint32_t*)&l0v;
        *(uint32_t*)&chi[base1 + col] = *(uint32_t*)&h1;
        *(uint32_t*)&clo[base1 + col] = *(uint32_t*)&l1v;
    }
}

// ---------------------------------------------------------------------------
extern "C" void kernel_launch(void* const* d_in, const int* in_sizes, int n_in,
                              void* d_out, int out_size)
{
    const float* x    = (const float*)d_in[0];
    const float* cosp = (const float*)d_in[1];
    const float* sinp = (const float*)d_in[2];
    const float* Wq   = (const float*)d_in[3];
    const float* Wk   = (const float*)d_in[4];
    const float* Wv   = (const float*)d_in[5];
    const float* Wo   = (const float*)d_in[6];
    float* out = (float*)d_out;

    float *qp, *kp, *vp;
    cudaGetSymbolAddress((void**)&qp, g_q);
    cudaGetSymbolAddress((void**)&kp, g_k);
    cudaGetSymbolAddress((void**)&vp, g_v);

    __nv_bfloat16 *xhi, *xlo, *wqhi, *wqlo, *wkhi, *wklo, *wvhi, *wvlo, *wohi, *wolo;
    __nv_bfloat16 *chi, *clo, *qhi, *qlo, *khi, *klo, *vhi, *vlo;
    cudaGetSymbolAddress((void**)&xhi, g_xhi);
    cudaGetSymbolAddress((void**)&xlo, g_xlo);
    cudaGetSymbolAddress((void**)&wqhi, g_wqhi);
    cudaGetSymbolAddress((void**)&wqlo, g_wqlo);
    cudaGetSymbolAddress((void**)&wkhi, g_wkhi);
    cudaGetSymbolAddress((void**)&wklo, g_wklo);
    cudaGetSymbolAddress((void**)&wvhi, g_wvhi);
    cudaGetSymbolAddress((void**)&wvlo, g_wvlo);
    cudaGetSymbolAddress((void**)&wohi, g_wohi);
    cudaGetSymbolAddress((void**)&wolo, g_wolo);
    cudaGetSymbolAddress((void**)&chi, g_chi);
    cudaGetSymbolAddress((void**)&clo, g_clo);
    cudaGetSymbolAddress((void**)&qhi, g_qhi);
    cudaGetSymbolAddress((void**)&qlo, g_qlo);
    cudaGetSymbolAddress((void**)&khi, g_khi);
    cudaGetSymbolAddress((void**)&klo, g_klo);
    cudaGetSymbolAddress((void**)&vhi, g_vhi);
    cudaGetSymbolAddress((void**)&vlo, g_vlo);

    const int M = B_ * S_;
    const int K = E_;

    // splits
    {
        int nx = M * E_ / 2;
        split_bf16<<<(nx + 255) / 256, 256>>>((const float2*)x,
            (__nv_bfloat162*)xhi, (__nv_bfloat162*)xlo, nx);
        int nq = H_ * D_ * E_ / 2;
        split_bf16<<<(nq + 255) / 256, 256>>>((const float2*)Wq,
            (__nv_bfloat162*)wqhi, (__nv_bfloat162*)wqlo, nq);
        int nk = KV_ * D_ * E_ / 2;
        split_bf16<<<(nk + 255) / 256, 256>>>((const float2*)Wk,
            (__nv_bfloat162*)wkhi, (__nv_bfloat162*)wklo, nk);
        split_bf16<<<(nk + 255) / 256, 256>>>((const float2*)Wv,
            (__nv_bfloat162*)wvhi, (__nv_bfloat162*)wvlo, nk);
        int no = E_ * H_ * D_ / 2;
        split_bf16<<<(no + 255) / 256, 256>>>((const float2*)Wo,
            (__nv_bfloat162*)wohi, (__nv_bfloat162*)wolo, no);
    }

    // projections
    gemm3<<<dim3((H_ * D_) / 128, M / 128), 256>>>(xhi, xlo, wqhi, wqlo, qp, M, H_ * D_, K);
    gemm3<<<dim3((KV_ * D_) / 128, M / 128), 256>>>(xhi, xlo, wkhi, wklo, kp, M, KV_ * D_, K);
    gemm3<<<dim3((KV_ * D_) / 128, M / 128), 256>>>(xhi, xlo, wvhi, wvlo, vp, M, KV_ * D_, K);

    // RoPE + RMSNorm -> bf16 hi/lo
    {
        int wq = M * H_;
        int wk = M * KV_;
        rope_rms_split<<<(wq + 3) / 4, 128>>>(qp, qhi, qlo, cosp, sinp, H_, wq);
        rope_rms_split<<<(wk + 3) / 4, 128>>>(kp, khi, klo, cosp, sinp, KV_, wk);
    }

    // V split
    {
        int nv = M * KV_ * D_ / 2;
        split_bf16<<<(nv + 255) / 256, 256>>>((const float2*)vp,
            (__nv_bfloat162*)vhi, (__nv_bfloat162*)vlo, nv);
    }

    // attention (tensor cores)
    {
        static bool attr_done = false;
        if (!attr_done) {
            cudaFuncSetAttribute(attn_mma,
                cudaFuncAttributeMaxDynamicSharedMemorySize, 8 * RB);
            attr_done = true;
        }
        attn_mma<<<dim3(S_ / 128, H_, B_), 256, 8 * RB>>>(
            qhi, qlo, khi, klo, vhi, vlo, chi, clo);
    }

    // output projection
    gemm3<<<dim3(E_ / 128, M / 128), 256>>>(chi, clo, wohi, wolo, out, M, E_, K);
}